// round 5
// baseline (speedup 1.0000x reference)
#include <cuda_runtime.h>
#include <cuda_bf16.h>
#include <cstdint>

// NeuralNetwork_28819230556388 — B=262144, D=64, 13 chained 64x64 GEMMs.
// mma.sync.m16n8k16 bf16, hi/lo 3-product split (fp32-grade accuracy).
// R5: two-slot register-resident activations (h_t overwrites h_{t-2} regs
// after the skip pass consumes them) + skip-pass-first layer structure so
// layer t's skip GEMM can overlap layer t-1's epilogue. Frees ~90 regs for
// ptxas prefetch scheduling. Weights resident in SMEM, persistent CTAs,
// zero barriers in the main loop.

#define TPB    256
#define GRID   148
#define NTILES 2048

// SMEM layout (bytes)
#define OFF_BN 0                     // 7*64 f32 = 1792
#define OFF_BS 1792                  // 6*64 f32 = 1536
#define OFF_W  4096                  // 13 mats * 16384 (hi at +0, lo at +8192)
#define SMEM_TOTAL (4096 + 26*8192)  // 217088

#define SMEM_SWIZZLE_128B(bo) ((bo) ^ (((bo) >> 3) & 0x70))

__device__ __forceinline__ uint32_t smem_to_u32(const void* p) {
    uint32_t a;
    asm("{ .reg .u64 t; cvta.to.shared.u64 t, %1; cvt.u32.u64 %0, t; }"
        : "=r"(a) : "l"(p));
    return a;
}

#define LDSM_X4(r, addr) \
    asm volatile("ldmatrix.sync.aligned.m8n8.x4.shared.b16 {%0,%1,%2,%3}, [%4];" \
        : "=r"((r)[0]), "=r"((r)[1]), "=r"((r)[2]), "=r"((r)[3]) \
        : "r"(addr))

__device__ __forceinline__ void mma_bf16(float d[4], const uint32_t a[4],
                                         uint32_t b0, uint32_t b1) {
    asm volatile(
        "mma.sync.aligned.m16n8k16.row.col.f32.bf16.bf16.f32 "
        "{%0,%1,%2,%3}, {%4,%5,%6,%7}, {%8,%9}, {%0,%1,%2,%3};"
        : "+f"(d[0]), "+f"(d[1]), "+f"(d[2]), "+f"(d[3])
        : "r"(a[0]), "r"(a[1]), "r"(a[2]), "r"(a[3]), "r"(b0), "r"(b1));
}

// split (a,b) into bf16 hi pair + bf16 residual pair (packed b32, a low)
__device__ __forceinline__ void pack_split(float a, float b,
                                           uint32_t& hi, uint32_t& lo) {
    __nv_bfloat162 h = __floats2bfloat162_rn(a, b);
    float ra = a - __bfloat162float(h.x);
    float rb = b - __bfloat162float(h.y);
    __nv_bfloat162 l = __floats2bfloat162_rn(ra, rb);
    hi = *reinterpret_cast<uint32_t*>(&h);
    lo = *reinterpret_cast<uint32_t*>(&l);
}

// 16 rows x 64 cols activation fragment, bf16 hi/lo A-frags [ktile][reg]
struct Frag {
    uint32_t h[4][4];
    uint32_t l[4][4];
};

// One layer. Ap = h_{t-1}. Aio holds h_{t-2} on entry (skip operand) and is
// OVERWRITTEN with h_t (pass 1 fully consumes it before pass 2 writes it).
// LAST: store fp32 result to gmem instead of packing.
template <bool HAS_SKIP, bool LAST>
__device__ __forceinline__ void layer_step(
    const Frag& Ap, Frag& Aio,
    uint32_t wn, uint32_t ws,
    const float* __restrict__ bnp, const float* __restrict__ bsp,
    uint32_t soff0, uint32_t soff1, int qt,
    float* __restrict__ out0, float* __restrict__ out1)
{
    // ---- pass 1: skip GEMM, all n-tiles, 3 products into ds ----
    float ds[4][2][4];
    if (HAS_SKIP) {
#pragma unroll
        for (int np = 0; np < 4; ++np) {
#pragma unroll
            for (int i2 = 0; i2 < 2; ++i2)
#pragma unroll
                for (int r = 0; r < 4; ++r) ds[np][i2][r] = 0.0f;

            uint32_t Bs[2][8];
#pragma unroll
            for (int i2 = 0; i2 < 2; ++i2) {
                uint32_t s = ws + (uint32_t)(2 * np + i2) * 1024;
                LDSM_X4(&Bs[i2][0], s + soff0);
                LDSM_X4(&Bs[i2][4], s + soff1);
            }
#pragma unroll
            for (int kt = 0; kt < 4; ++kt)
#pragma unroll
                for (int i2 = 0; i2 < 2; ++i2)
                    mma_bf16(ds[np][i2], Aio.h[kt], Bs[i2][2 * kt], Bs[i2][2 * kt + 1]);
#pragma unroll
            for (int kt = 0; kt < 4; ++kt)
#pragma unroll
                for (int i2 = 0; i2 < 2; ++i2)
                    mma_bf16(ds[np][i2], Aio.l[kt], Bs[i2][2 * kt], Bs[i2][2 * kt + 1]);
#pragma unroll
            for (int i2 = 0; i2 < 2; ++i2) {
                uint32_t s = ws + 8192u + (uint32_t)(2 * np + i2) * 1024;
                LDSM_X4(&Bs[i2][0], s + soff0);
                LDSM_X4(&Bs[i2][4], s + soff1);
            }
#pragma unroll
            for (int kt = 0; kt < 4; ++kt)
#pragma unroll
                for (int i2 = 0; i2 < 2; ++i2)
                    mma_bf16(ds[np][i2], Aio.h[kt], Bs[i2][2 * kt], Bs[i2][2 * kt + 1]);
        }
    }

    // ---- pass 2: next GEMM per n-tile + epilogue (writes Aio in place) ----
#pragma unroll
    for (int np = 0; np < 4; ++np) {
        float dn[2][4];
#pragma unroll
        for (int i2 = 0; i2 < 2; ++i2)
#pragma unroll
            for (int r = 0; r < 4; ++r) dn[i2][r] = 0.0f;

        uint32_t Bn[2][8];
#pragma unroll
        for (int i2 = 0; i2 < 2; ++i2) {
            uint32_t a = wn + (uint32_t)(2 * np + i2) * 1024;
            LDSM_X4(&Bn[i2][0], a + soff0);
            LDSM_X4(&Bn[i2][4], a + soff1);
        }
#pragma unroll
        for (int kt = 0; kt < 4; ++kt)
#pragma unroll
            for (int i2 = 0; i2 < 2; ++i2)
                mma_bf16(dn[i2], Ap.h[kt], Bn[i2][2 * kt], Bn[i2][2 * kt + 1]);
#pragma unroll
        for (int kt = 0; kt < 4; ++kt)
#pragma unroll
            for (int i2 = 0; i2 < 2; ++i2)
                mma_bf16(dn[i2], Ap.l[kt], Bn[i2][2 * kt], Bn[i2][2 * kt + 1]);
#pragma unroll
        for (int i2 = 0; i2 < 2; ++i2) {
            uint32_t a = wn + 8192u + (uint32_t)(2 * np + i2) * 1024;
            LDSM_X4(&Bn[i2][0], a + soff0);
            LDSM_X4(&Bn[i2][4], a + soff1);
        }
#pragma unroll
        for (int kt = 0; kt < 4; ++kt)
#pragma unroll
            for (int i2 = 0; i2 < 2; ++i2)
                mma_bf16(dn[i2], Ap.h[kt], Bn[i2][2 * kt], Bn[i2][2 * kt + 1]);

        // epilogue: bias + relu (+skip), then C-frag -> A-frag in place
#pragma unroll
        for (int i2 = 0; i2 < 2; ++i2) {
            const int nt = 2 * np + i2;
            float b0 = bnp[8 * nt + 2 * qt];
            float b1 = bnp[8 * nt + 2 * qt + 1];
            float v0 = fmaxf(dn[i2][0] + b0, 0.0f);
            float v1 = fmaxf(dn[i2][1] + b1, 0.0f);
            float v2 = fmaxf(dn[i2][2] + b0, 0.0f);
            float v3 = fmaxf(dn[i2][3] + b1, 0.0f);
            if (HAS_SKIP) {
                float s0 = bsp[8 * nt + 2 * qt];
                float s1 = bsp[8 * nt + 2 * qt + 1];
                v0 += fmaxf(ds[np][i2][0] + s0, 0.0f);
                v1 += fmaxf(ds[np][i2][1] + s1, 0.0f);
                v2 += fmaxf(ds[np][i2][2] + s0, 0.0f);
                v3 += fmaxf(ds[np][i2][3] + s1, 0.0f);
            }
            if (LAST) {
                float2* p0 = reinterpret_cast<float2*>(out0 + 8 * nt + 2 * qt);
                float2* p1 = reinterpret_cast<float2*>(out1 + 8 * nt + 2 * qt);
                *p0 = make_float2(v0, v1);
                *p1 = make_float2(v2, v3);
            } else {
                pack_split(v0, v1, Aio.h[np][2 * i2],     Aio.l[np][2 * i2]);
                pack_split(v2, v3, Aio.h[np][2 * i2 + 1], Aio.l[np][2 * i2 + 1]);
            }
        }
    }
}

__global__ void __launch_bounds__(TPB, 1)
nn_mma_kernel(const float* __restrict__ x,
              const float* __restrict__ Wn_g,
              const float* __restrict__ bn_g,
              const float* __restrict__ Ws_g,
              const float* __restrict__ bs_g,
              float* __restrict__ out)
{
    extern __shared__ unsigned char sm[];
    const uint32_t smb = smem_to_u32(sm);
    const int tid  = threadIdx.x;
    const int wid  = tid >> 5;
    const int lane = tid & 31;
    const int qt   = lane & 3;
    const int grp  = lane >> 2;

    // ---- stage 13 weight matrices as bf16 hi/lo, [n][k] row-major, SW128 ----
    for (int idx = tid; idx < 13 * 4096; idx += TPB) {
        int mat = idx >> 12, e = idx & 4095;
        float v = (mat < 7) ? Wn_g[mat * 4096 + e] : Ws_g[(mat - 7) * 4096 + e];
        __nv_bfloat16 hb = __float2bfloat16(v);
        __nv_bfloat16 lb = __float2bfloat16(v - __bfloat162float(hb));
        int n = e >> 6, k = e & 63;
        uint32_t sw = SMEM_SWIZZLE_128B((uint32_t)(n * 128 + k * 2));
        uint32_t base = OFF_W + (uint32_t)mat * 16384;
        *reinterpret_cast<__nv_bfloat16*>(sm + base + sw)        = hb;
        *reinterpret_cast<__nv_bfloat16*>(sm + base + 8192 + sw) = lb;
    }
    for (int i = tid; i < 448; i += TPB)
        reinterpret_cast<float*>(sm + OFF_BN)[i] = bn_g[i];
    for (int i = tid; i < 384; i += TPB)
        reinterpret_cast<float*>(sm + OFF_BS)[i] = bs_g[i];
    __syncthreads();

    // per-thread ldmatrix.x4 swizzled offsets (k halves 0-31 / 32-63)
    const int r8 = lane & 7, b4 = lane >> 3;
    const uint32_t soff0 = (uint32_t)(r8 * 128 + ((b4 * 16)      ^ (r8 * 16)));
    const uint32_t soff1 = (uint32_t)(r8 * 128 + ((b4 * 16 + 64) ^ (r8 * 16)));

    const float* bn = reinterpret_cast<const float*>(sm + OFF_BN);
    const float* bs = reinterpret_cast<const float*>(sm + OFF_BS);
    const uint32_t w0 = smb + OFF_W;

    const int row0 = wid * 16 + grp;
    const int row1 = row0 + 8;

    for (int tile = blockIdx.x; tile < NTILES; tile += GRID) {
        const size_t gr0 = (size_t)tile * 128 + row0;
        const size_t gr1 = (size_t)tile * 128 + row1;

        Frag A0, A1;   // two slots; h_t overwrites the slot holding h_{t-2}

        // ---- load x -> A0 (hi/lo) directly from gmem ----
        {
            const float* xr0 = x + gr0 * 64;
            const float* xr1 = x + gr1 * 64;
#pragma unroll
            for (int kt = 0; kt < 4; ++kt) {
                const int c = 16 * kt + 2 * qt;
                float2 p0 = *reinterpret_cast<const float2*>(xr0 + c);
                float2 p1 = *reinterpret_cast<const float2*>(xr1 + c);
                float2 p2 = *reinterpret_cast<const float2*>(xr0 + c + 8);
                float2 p3 = *reinterpret_cast<const float2*>(xr1 + c + 8);
                pack_split(p0.x, p0.y, A0.h[kt][0], A0.l[kt][0]);
                pack_split(p1.x, p1.y, A0.h[kt][1], A0.l[kt][1]);
                pack_split(p2.x, p2.y, A0.h[kt][2], A0.l[kt][2]);
                pack_split(p3.x, p3.y, A0.h[kt][3], A0.l[kt][3]);
            }
        }

        float* o0 = out + gr0 * 64;
        float* o1 = out + gr1 * 64;

        // layer t: Ap = h_{t-1}, Aio = h_{t-2} -> h_t
        layer_step<false, false>(A0, A1, w0 + 0 * 16384, 0,
                                 bn + 0 * 64, bs, soff0, soff1, qt, o0, o1);           // h1 -> A1
        layer_step<true,  false>(A1, A0, w0 + 1 * 16384, w0 + 7 * 16384,
                                 bn + 1 * 64, bs + 0 * 64, soff0, soff1, qt, o0, o1);  // h2 -> A0
        layer_step<true,  false>(A0, A1, w0 + 2 * 16384, w0 + 8 * 16384,
                                 bn + 2 * 64, bs + 1 * 64, soff0, soff1, qt, o0, o1);  // h3 -> A1
        layer_step<true,  false>(A1, A0, w0 + 3 * 16384, w0 + 9 * 16384,
                                 bn + 3 * 64, bs + 2 * 64, soff0, soff1, qt, o0, o1);  // h4 -> A0
        layer_step<true,  false>(A0, A1, w0 + 4 * 16384, w0 + 10 * 16384,
                                 bn + 4 * 64, bs + 3 * 64, soff0, soff1, qt, o0, o1);  // h5 -> A1
        layer_step<true,  false>(A1, A0, w0 + 5 * 16384, w0 + 11 * 16384,
                                 bn + 5 * 64, bs + 4 * 64, soff0, soff1, qt, o0, o1);  // h6 -> A0
        layer_step<true,  true >(A0, A1, w0 + 6 * 16384, w0 + 12 * 16384,
                                 bn + 6 * 64, bs + 5 * 64, soff0, soff1, qt, o0, o1);  // h7 -> out
    }
}

extern "C" void kernel_launch(void* const* d_in, const int* in_sizes, int n_in,
                              void* d_out, int out_size)
{
    const float* x  = (const float*)d_in[0];
    const float* Wn = (const float*)d_in[1];
    const float* bn = (const float*)d_in[2];
    const float* Ws = (const float*)d_in[3];
    const float* bs = (const float*)d_in[4];
    float* out = (float*)d_out;

    cudaFuncSetAttribute(nn_mma_kernel,
                         cudaFuncAttributeMaxDynamicSharedMemorySize, SMEM_TOTAL);
    nn_mma_kernel<<<GRID, TPB, SMEM_TOTAL>>>(x, Wn, bn, Ws, bs, out);
}